// round 3
// baseline (speedup 1.0000x reference)
#include <cuda_runtime.h>

typedef unsigned long long u64;

// ---------- packed f32x2 helpers (Blackwell sm_100+) ----------
__device__ __forceinline__ u64 pk2(float a, float b) {
    u64 r; asm("mov.b64 %0,{%1,%2};" : "=l"(r) : "f"(a), "f"(b)); return r;
}
__device__ __forceinline__ float2 upk(u64 v) {
    float2 r; asm("mov.b64 {%0,%1},%2;" : "=f"(r.x), "=f"(r.y) : "l"(v)); return r;
}
__device__ __forceinline__ u64 fma2(u64 a, u64 b, u64 c) {
    u64 d; asm("fma.rn.f32x2 %0,%1,%2,%3;" : "=l"(d) : "l"(a), "l"(b), "l"(c)); return d;
}
__device__ __forceinline__ u64 mul2(u64 a, u64 b) {
    u64 d; asm("mul.rn.f32x2 %0,%1,%2;" : "=l"(d) : "l"(a), "l"(b)); return d;
}
__device__ __forceinline__ u64 add2(u64 a, u64 b) {
    u64 d; asm("add.rn.f32x2 %0,%1,%2;" : "=l"(d) : "l"(a), "l"(b)); return d;
}
__device__ __forceinline__ u64 neg2(u64 a) {
    u64 r; asm("xor.b64 %0,%1,%2;" : "=l"(r) : "l"(a), "l"(0x8000000080000000ULL));
    return r;
}
__device__ __forceinline__ u64 sub2(u64 a, u64 b) { return add2(a, neg2(b)); }

// One line per thread. Lane 0 = u-stream (qubits 0,1), lane 1 = v-stream
// (qubits 2,3). The two streams are structurally identical, so all packed
// ops do double duty; only the final Z1/Z2 coupling unpacks.
__global__ __launch_bounds__(128)
void qcnn_kernel(const float* __restrict__ x, const float* __restrict__ w,
                 float* __restrict__ out, int n) {
    // sg[s][k]: layer-1 gate constants, stream s (0: gates for qubits 0&2 in
    // lanes 0&1; 1: gates for qubits 1&3). 10 constants per gate:
    // {u00r,u00i,u01r,-u01i,u01i, u10r,u10i,u11r,-u11i,u11i}
    __shared__ u64 sg[2][10];
    // so[s][j]: observables {a, 2b, -2c} packed the same way
    __shared__ u64 so[2][3];

    int tid = threadIdx.x;
    if (tid < 8) {
        int h = tid >> 2, q = tid & 3;
        int s = q & 1, l = q >> 1;     // stream, lane
        const float* wp = w + h * 12 + q * 3;
        float a = wp[0], b = wp[1], g = wp[2];
        float sa, ca, sb, cb, sgg, cgg;
        sincosf(0.5f * a, &sa, &ca);
        sincosf(0.5f * b, &sb, &cb);
        sincosf(0.5f * g, &sgg, &cgg);
        // M = RY * RX
        float m00r = cb * ca, m00i =  sb * sa;
        float m01r = -sb * ca, m01i = -cb * sa;
        float m10r =  sb * ca, m10i = -cb * sa;
        float m11r =  cb * ca, m11i = -sb * sa;
        // U = RZ * M
        float u00r = cgg * m00r + sgg * m00i, u00i = cgg * m00i - sgg * m00r;
        float u01r = cgg * m01r + sgg * m01i, u01i = cgg * m01i - sgg * m01r;
        float u10r = cgg * m10r - sgg * m10i, u10i = cgg * m10i + sgg * m10r;
        float u11r = cgg * m11r - sgg * m11i, u11i = cgg * m11i + sgg * m11r;
        if (h == 0) {
            float* gp = (float*)&sg[s][0];
            gp[0*2+l] = u00r;  gp[1*2+l] = u00i;  gp[2*2+l] = u01r;
            gp[3*2+l] = -u01i; gp[4*2+l] = u01i;
            gp[5*2+l] = u10r;  gp[6*2+l] = u10i;  gp[7*2+l] = u11r;
            gp[8*2+l] = -u11i; gp[9*2+l] = u11i;
        } else {
            // M_q = U^dag Z U = [[a, b+ic],[b-ic, -a]]
            float ma = u00r * u00r + u00i * u00i - u10r * u10r - u10i * u10i;
            float mb = u00r * u01r + u00i * u01i - (u10r * u11r + u10i * u11i);
            float mc = u00r * u01i - u00i * u01r - (u10r * u11i - u10i * u11r);
            float* op = (float*)&so[s][0];
            op[0*2+l] = ma;
            op[1*2+l] = 2.f * mb;
            op[2*2+l] = -2.f * mc;
        }
    }
    __syncthreads();

    int t = blockIdx.x * 128 + tid;
    if (t >= n) return;

    // one line = 12 contiguous floats = 3 float4 loads (48B, aligned)
    const float4* xb = (const float4*)(x + (size_t)t * 12);
    float4 F0 = __ldg(xb + 0), F1 = __ldg(xb + 1), F2 = __ldg(xb + 2);

    const float PIH = 1.57079632679489662f;
    // per-qubit trig of x1 (RY angle/2) and x2 (RZ angle/2); RZ(pi*x0)|0> is
    // a global phase -> dropped
    float sb0, cb0, sz0, cz0, sb1, cb1, sz1, cz1;
    float sb2, cb2, sz2, cz2, sb3, cb3, sz3, cz3;
    __sincosf(PIH * F0.y, &sb0, &cb0);  __sincosf(PIH * F0.z, &sz0, &cz0);
    __sincosf(PIH * F1.x, &sb1, &cb1);  __sincosf(PIH * F1.y, &sz1, &cz1);
    __sincosf(PIH * F1.w, &sb2, &cb2);  __sincosf(PIH * F2.x, &sz2, &cz2);
    __sincosf(PIH * F2.z, &sb3, &cb3);  __sincosf(PIH * F2.w, &sz3, &cz3);

    // pack: stream A lanes [q0,q2], stream B lanes [q1,q3]
    u64 cbA = pk2(cb0, cb2), sbA = pk2(sb0, sb2);
    u64 czA = pk2(cz0, cz2), szA = pk2(sz0, sz2);
    u64 cbB = pk2(cb1, cb3), sbB = pk2(sb1, sb3);
    u64 czB = pk2(cz1, cz3), szB = pk2(sz1, sz3);

    // encoding vector (u0r, -t0, u1r, +t1) then layer-1 gate, signs folded
    // into the constant indexing
    u64 a0r, a0i, a1r, a1i;
    {
        u64 u0r = mul2(cbA, czA), t0 = mul2(cbA, szA);
        u64 u1r = mul2(sbA, czA), t1 = mul2(sbA, szA);
        u64 t0n = neg2(t0);
        const u64* k = sg[0];
        a0r = fma2(k[3], t1, fma2(k[2], u1r, fma2(k[1], t0,  mul2(k[0], u0r))));
        a0i = fma2(k[2], t1, fma2(k[4], u1r, fma2(k[0], t0n, mul2(k[1], u0r))));
        a1r = fma2(k[8], t1, fma2(k[7], u1r, fma2(k[6], t0,  mul2(k[5], u0r))));
        a1i = fma2(k[7], t1, fma2(k[9], u1r, fma2(k[5], t0n, mul2(k[6], u0r))));
    }
    u64 b0r, b0i, b1r, b1i;
    {
        u64 u0r = mul2(cbB, czB), t0 = mul2(cbB, szB);
        u64 u1r = mul2(sbB, czB), t1 = mul2(sbB, szB);
        u64 t0n = neg2(t0);
        const u64* k = sg[1];
        b0r = fma2(k[3], t1, fma2(k[2], u1r, fma2(k[1], t0,  mul2(k[0], u0r))));
        b0i = fma2(k[2], t1, fma2(k[4], u1r, fma2(k[0], t0n, mul2(k[1], u0r))));
        b1r = fma2(k[8], t1, fma2(k[7], u1r, fma2(k[6], t0,  mul2(k[5], u0r))));
        b1i = fma2(k[7], t1, fma2(k[9], u1r, fma2(k[5], t0n, mul2(k[6], u0r))));
    }

    // pair product p = A (x) B, with CZ(0,1)/CZ(2,3) folded (p3 negated).
    // lanes: [u0..u3 | v0..v3]
    u64 nb0i = neg2(b0i), nb1i = neg2(b1i);
    u64 p0r = fma2(a0i, nb0i, mul2(a0r, b0r)), p0i = fma2(a0i, b0r, mul2(a0r, b0i));
    u64 p1r = fma2(a0i, nb1i, mul2(a0r, b1r)), p1i = fma2(a0i, b1r, mul2(a0r, b1i));
    u64 p2r = fma2(a1i, nb0i, mul2(a1r, b0r)), p2i = fma2(a1i, b0r, mul2(a1r, b0i));
    u64 p3r = neg2(fma2(a1i, nb1i, mul2(a1r, b1r)));
    u64 p3i = neg2(fma2(a1i, b1r, mul2(a1r, b1i)));

    // probabilities and diagonal-Z combos (pair norms are 1)
    u64 P0 = fma2(p0i, p0i, mul2(p0r, p0r));
    u64 P1 = fma2(p1i, p1i, mul2(p1r, p1r));
    u64 P2 = fma2(p2i, p2i, mul2(p2r, p2r));
    u64 P3 = fma2(p3i, p3i, mul2(p3r, p3r));
    u64 DA = sub2(add2(P0, P1), add2(P2, P3));   // [Du0, Dv2]
    u64 DB = add2(sub2(P0, P1), sub2(P2, P3));   // [Du1, Dv3]

    // cross terms: XA = conj(p0)p2 + conj(p1)p3 -> [X0, X2]
    //              XB = conj(p0)p1 + conj(p2)p3 -> [X1, X3]
    u64 ReXA = fma2(p1i, p3i, fma2(p1r, p3r, fma2(p0i, p2i, mul2(p0r, p2r))));
    u64 ImXA = fma2(p1r, p3i, fma2(p0r, p2i,
               neg2(fma2(p1i, p3r, mul2(p0i, p2r)))));
    u64 ReXB = fma2(p2i, p3i, fma2(p2r, p3r, fma2(p0i, p1i, mul2(p0r, p1r))));
    u64 ImXB = fma2(p2r, p3i, fma2(p0r, p1i,
               neg2(fma2(p2i, p3r, mul2(p0i, p1r)))));

    // observable contraction (CZ(1,2) handled below via Du1/Dv2 coupling)
    u64 CA = fma2(so[0][2], ImXA, mul2(so[0][1], ReXA));  // [cross0, cross2]
    u64 CB = fma2(so[1][2], ImXB, mul2(so[1][1], ReXB));  // [cross1, cross3]
    u64 GA = mul2(so[0][0], DA);                          // [a0*Du0, a2*Dv2]
    u64 GB = mul2(so[1][0], DB);                          // [a1*Du1, a3*Dv3]

    float2 dA = upk(DA), dB = upk(DB);
    float2 ca = upk(CA), cb_ = upk(CB), ga = upk(GA), gb = upk(GB);
    float z0 = ga.x + ca.x;
    float z1 = fmaf(cb_.x, dA.y, gb.x);   // cross1 * Dv2
    float z2 = fmaf(ca.y, dB.x, ga.y);    // cross2 * Du1
    float z3 = gb.y + cb_.y;

    ((float4*)out)[t] = make_float4(z0, z1, z2, z3);
}

extern "C" void kernel_launch(void* const* d_in, const int* in_sizes, int n_in,
                              void* d_out, int out_size) {
    const float* x = (const float*)d_in[0];   // [128, 2048, 4, 3] f32
    const float* w = (const float*)d_in[1];   // [2, 4, 3] f32
    float* out = (float*)d_out;               // [128, 2048, 4] f32

    int nlines = in_sizes[0] / 12;            // 262144
    int block = 128;
    int grid = (nlines + block - 1) / block;  // 2048
    qcnn_kernel<<<grid, block>>>(x, w, out, nlines);
}

// round 4
// speedup vs baseline: 1.0295x; 1.0295x over previous
#include <cuda_runtime.h>

typedef unsigned long long u64;

// ---------- packed f32x2 helpers (Blackwell sm_100+) ----------
__device__ __forceinline__ u64 pk2(float a, float b) {
    u64 r; asm("mov.b64 %0,{%1,%2};" : "=l"(r) : "f"(a), "f"(b)); return r;
}
__device__ __forceinline__ float2 upk(u64 v) {
    float2 r; asm("mov.b64 {%0,%1},%2;" : "=f"(r.x), "=f"(r.y) : "l"(v)); return r;
}
__device__ __forceinline__ u64 fma2(u64 a, u64 b, u64 c) {
    u64 d; asm("fma.rn.f32x2 %0,%1,%2,%3;" : "=l"(d) : "l"(a), "l"(b), "l"(c)); return d;
}
__device__ __forceinline__ u64 mul2(u64 a, u64 b) {
    u64 d; asm("mul.rn.f32x2 %0,%1,%2;" : "=l"(d) : "l"(a), "l"(b)); return d;
}
__device__ __forceinline__ u64 add2(u64 a, u64 b) {
    u64 d; asm("add.rn.f32x2 %0,%1,%2;" : "=l"(d) : "l"(a), "l"(b)); return d;
}
__device__ __forceinline__ u64 neg2(u64 a) {
    u64 r; asm("xor.b64 %0,%1,%2;" : "=l"(r) : "l"(a), "l"(0x8000000080000000ULL));
    return r;
}
__device__ __forceinline__ u64 sub2(u64 a, u64 b) { return add2(a, neg2(b)); }

// One line per thread. Lane 0 = u-stream (qubits 0,1), lane 1 = v-stream
// (qubits 2,3). The two streams are structurally identical, so all packed
// ops do double duty; only the final Z1/Z2 coupling unpacks.
__global__ __launch_bounds__(256)
void qcnn_kernel(const float* __restrict__ x, const float* __restrict__ w,
                 float* __restrict__ out, int n) {
    // sg[s][k]: layer-1 gate constants, stream s (lanes = [qubit s, qubit s+2]).
    // 10 constants per gate: {u00r,u00i,u01r,-u01i,u01i, u10r,u10i,u11r,-u11i,u11i}
    __shared__ u64 sg[2][10];
    // so[s][j]: observables {a, 2b, -2c} packed the same way
    __shared__ u64 so[2][3];

    int tid = threadIdx.x;
    int t = blockIdx.x * 256 + tid;

    // Issue global loads FIRST so DRAM latency overlaps the gate precompute
    // and the barrier below. One line = 12 contiguous floats = 3 float4s.
    const float4* xb = (const float4*)(x + (size_t)t * 12);
    float4 F0 = __ldg(xb + 0), F1 = __ldg(xb + 1), F2 = __ldg(xb + 2);

    if (tid < 8) {
        int h = tid >> 2, q = tid & 3;
        int s = q & 1, l = q >> 1;     // stream, lane
        const float* wp = w + h * 12 + q * 3;
        float a = wp[0], b = wp[1], g = wp[2];
        // w ~ N(0,1): |angle/2| small -> fast MUFU sin/cos is plenty accurate
        float sa, ca, sb, cb, sgg, cgg;
        __sincosf(0.5f * a, &sa, &ca);
        __sincosf(0.5f * b, &sb, &cb);
        __sincosf(0.5f * g, &sgg, &cgg);
        // M = RY * RX
        float m00r = cb * ca, m00i =  sb * sa;
        float m01r = -sb * ca, m01i = -cb * sa;
        float m10r =  sb * ca, m10i = -cb * sa;
        float m11r =  cb * ca, m11i = -sb * sa;
        // U = RZ * M
        float u00r = cgg * m00r + sgg * m00i, u00i = cgg * m00i - sgg * m00r;
        float u01r = cgg * m01r + sgg * m01i, u01i = cgg * m01i - sgg * m01r;
        float u10r = cgg * m10r - sgg * m10i, u10i = cgg * m10i + sgg * m10r;
        float u11r = cgg * m11r - sgg * m11i, u11i = cgg * m11i + sgg * m11r;
        if (h == 0) {
            float* gp = (float*)&sg[s][0];
            gp[0*2+l] = u00r;  gp[1*2+l] = u00i;  gp[2*2+l] = u01r;
            gp[3*2+l] = -u01i; gp[4*2+l] = u01i;
            gp[5*2+l] = u10r;  gp[6*2+l] = u10i;  gp[7*2+l] = u11r;
            gp[8*2+l] = -u11i; gp[9*2+l] = u11i;
        } else {
            // M_q = U^dag Z U = [[a, b+ic],[b-ic, -a]]
            float ma = u00r * u00r + u00i * u00i - u10r * u10r - u10i * u10i;
            float mb = u00r * u01r + u00i * u01i - (u10r * u11r + u10i * u11i);
            float mc = u00r * u01i - u00i * u01r - (u10r * u11i - u10i * u11r);
            float* op = (float*)&so[s][0];
            op[0*2+l] = ma;
            op[1*2+l] = 2.f * mb;
            op[2*2+l] = -2.f * mc;
        }
    }
    __syncthreads();

    if (t >= n) return;

    const float PIH = 1.57079632679489662f;
    // per-qubit trig of x1 (RY angle/2) and x2 (RZ angle/2); RZ(pi*x0)|0> is
    // a global phase -> dropped
    float sb0, cb0, sz0, cz0, sb1, cb1, sz1, cz1;
    float sb2, cb2, sz2, cz2, sb3, cb3, sz3, cz3;
    __sincosf(PIH * F0.y, &sb0, &cb0);  __sincosf(PIH * F0.z, &sz0, &cz0);
    __sincosf(PIH * F1.x, &sb1, &cb1);  __sincosf(PIH * F1.y, &sz1, &cz1);
    __sincosf(PIH * F1.w, &sb2, &cb2);  __sincosf(PIH * F2.x, &sz2, &cz2);
    __sincosf(PIH * F2.z, &sb3, &cb3);  __sincosf(PIH * F2.w, &sz3, &cz3);

    // pack: stream A lanes [q0,q2], stream B lanes [q1,q3]
    u64 cbA = pk2(cb0, cb2), sbA = pk2(sb0, sb2);
    u64 czA = pk2(cz0, cz2), szA = pk2(sz0, sz2);
    u64 cbB = pk2(cb1, cb3), sbB = pk2(sb1, sb3);
    u64 czB = pk2(cz1, cz3), szB = pk2(sz1, sz3);

    // encoding vector (u0r, -t0, u1r, +t1) then layer-1 gate, signs folded
    // into the constant indexing
    u64 a0r, a0i, a1r, a1i;
    {
        u64 u0r = mul2(cbA, czA), t0 = mul2(cbA, szA);
        u64 u1r = mul2(sbA, czA), t1 = mul2(sbA, szA);
        u64 t0n = neg2(t0);
        const u64* k = sg[0];
        a0r = fma2(k[3], t1, fma2(k[2], u1r, fma2(k[1], t0,  mul2(k[0], u0r))));
        a0i = fma2(k[2], t1, fma2(k[4], u1r, fma2(k[0], t0n, mul2(k[1], u0r))));
        a1r = fma2(k[8], t1, fma2(k[7], u1r, fma2(k[6], t0,  mul2(k[5], u0r))));
        a1i = fma2(k[7], t1, fma2(k[9], u1r, fma2(k[5], t0n, mul2(k[6], u0r))));
    }
    u64 b0r, b0i, b1r, b1i;
    {
        u64 u0r = mul2(cbB, czB), t0 = mul2(cbB, szB);
        u64 u1r = mul2(sbB, czB), t1 = mul2(sbB, szB);
        u64 t0n = neg2(t0);
        const u64* k = sg[1];
        b0r = fma2(k[3], t1, fma2(k[2], u1r, fma2(k[1], t0,  mul2(k[0], u0r))));
        b0i = fma2(k[2], t1, fma2(k[4], u1r, fma2(k[0], t0n, mul2(k[1], u0r))));
        b1r = fma2(k[8], t1, fma2(k[7], u1r, fma2(k[6], t0,  mul2(k[5], u0r))));
        b1i = fma2(k[7], t1, fma2(k[9], u1r, fma2(k[5], t0n, mul2(k[6], u0r))));
    }

    // pair product p = A (x) B, with CZ(0,1)/CZ(2,3) folded (p3 negated).
    u64 nb0i = neg2(b0i), nb1i = neg2(b1i);
    u64 p0r = fma2(a0i, nb0i, mul2(a0r, b0r)), p0i = fma2(a0i, b0r, mul2(a0r, b0i));
    u64 p1r = fma2(a0i, nb1i, mul2(a0r, b1r)), p1i = fma2(a0i, b1r, mul2(a0r, b1i));
    u64 p2r = fma2(a1i, nb0i, mul2(a1r, b0r)), p2i = fma2(a1i, b0r, mul2(a1r, b0i));
    u64 p3r = neg2(fma2(a1i, nb1i, mul2(a1r, b1r)));
    u64 p3i = neg2(fma2(a1i, b1r, mul2(a1r, b1i)));

    // probabilities and diagonal-Z combos (pair norms are 1)
    u64 P0 = fma2(p0i, p0i, mul2(p0r, p0r));
    u64 P1 = fma2(p1i, p1i, mul2(p1r, p1r));
    u64 P2 = fma2(p2i, p2i, mul2(p2r, p2r));
    u64 P3 = fma2(p3i, p3i, mul2(p3r, p3r));
    u64 DA = sub2(add2(P0, P1), add2(P2, P3));   // [Du0, Dv2]
    u64 DB = add2(sub2(P0, P1), sub2(P2, P3));   // [Du1, Dv3]

    // cross terms: XA = conj(p0)p2 + conj(p1)p3 -> [X0, X2]
    //              XB = conj(p0)p1 + conj(p2)p3 -> [X1, X3]
    u64 ReXA = fma2(p1i, p3i, fma2(p1r, p3r, fma2(p0i, p2i, mul2(p0r, p2r))));
    u64 ImXA = fma2(p1r, p3i, fma2(p0r, p2i,
               neg2(fma2(p1i, p3r, mul2(p0i, p2r)))));
    u64 ReXB = fma2(p2i, p3i, fma2(p2r, p3r, fma2(p0i, p1i, mul2(p0r, p1r))));
    u64 ImXB = fma2(p2r, p3i, fma2(p0r, p1i,
               neg2(fma2(p2i, p3r, mul2(p0i, p1r)))));

    // observable contraction (CZ(1,2) handled below via Du1/Dv2 coupling)
    u64 CA = fma2(so[0][2], ImXA, mul2(so[0][1], ReXA));  // [cross0, cross2]
    u64 CB = fma2(so[1][2], ImXB, mul2(so[1][1], ReXB));  // [cross1, cross3]
    u64 GA = mul2(so[0][0], DA);                          // [a0*Du0, a2*Dv2]
    u64 GB = mul2(so[1][0], DB);                          // [a1*Du1, a3*Dv3]

    float2 dA = upk(DA), dB = upk(DB);
    float2 ca = upk(CA), cb_ = upk(CB), ga = upk(GA), gb = upk(GB);
    float z0 = ga.x + ca.x;
    float z1 = fmaf(cb_.x, dA.y, gb.x);   // cross1 * Dv2
    float z2 = fmaf(ca.y, dB.x, ga.y);    // cross2 * Du1
    float z3 = gb.y + cb_.y;

    ((float4*)out)[t] = make_float4(z0, z1, z2, z3);
}

extern "C" void kernel_launch(void* const* d_in, const int* in_sizes, int n_in,
                              void* d_out, int out_size) {
    const float* x = (const float*)d_in[0];   // [128, 2048, 4, 3] f32
    const float* w = (const float*)d_in[1];   // [2, 4, 3] f32
    float* out = (float*)d_out;               // [128, 2048, 4] f32

    int nlines = in_sizes[0] / 12;            // 262144
    int block = 256;
    int grid = (nlines + block - 1) / block;  // 1024
    qcnn_kernel<<<grid, block>>>(x, w, out, nlines);
}